// round 16
// baseline (speedup 1.0000x reference)
#include <cuda_runtime.h>
#include <math.h>

typedef unsigned long long u64;

// ---------------- shapes ----------------
#define BERT 768
#define CTRY 24
#define CODE 8
#define GAZ  9
#define MIX  24
#define NFEAT 13
#define CMAX 64
#define B_MAX 2048
#define NCTRY_MAX 512
#define NCODES_MAX 1024

// ---------------- device scratch ----------------
__device__ float g_cet [NCTRY_MAX * CTRY];   // projected country embeddings (raw)
__device__ float g_cetn[NCTRY_MAX];          // their norms
__device__ float g_proj[B_MAX * 80];         // x(24)|x_code(8)|x_other(24)|x_doc(24)
__device__ int   g_flag[256];                // per (job,tile) proj-done flags
__device__ int   g_aux;                      // cet-blocks done counter

// ---------------- helpers ----------------
__device__ __forceinline__ void ffma2(u64& d, u64 a, u64 b) {
    asm("fma.rn.f32x2 %0, %1, %2, %0;" : "+l"(d) : "l"(a), "l"(b));
}
__device__ __forceinline__ u64 pack2(float lo, float hi) {
    u64 r; asm("mov.b64 %0, {%1,%2};" : "=l"(r) : "f"(lo), "f"(hi)); return r;
}
__device__ __forceinline__ void unpack2(u64 v, float& lo, float& hi) {
    asm("mov.b64 {%0,%1}, %2;" : "=f"(lo), "=f"(hi) : "l"(v));
}
__device__ __forceinline__ float hsum2(u64 v) {
    float lo, hi; unpack2(v, lo, hi); return lo + hi;
}
__device__ __forceinline__ float sumsq2(u64 v) {
    float lo, hi; unpack2(v, lo, hi); return lo * lo + hi * hi;
}
__device__ __forceinline__ float sigf(float x) {
    float t; asm("tanh.approx.f32 %0, %1;" : "=f"(t) : "f"(x * 0.5f));
    return fmaf(0.5f, t, 0.5f);
}
__device__ __forceinline__ float to_tf32(float x) {
    float y; asm("cvt.rna.tf32.f32 %0, %1;" : "=f"(y) : "f"(x)); return y;
}
__device__ __forceinline__ void mma_tf32(float* c,
    float a0, float a1, float a2, float a3, float b0, float b1)
{
    asm volatile(
        "mma.sync.aligned.m16n8k8.row.col.f32.tf32.tf32.f32 "
        "{%0,%1,%2,%3}, {%4,%5,%6,%7}, {%8,%9}, {%0,%1,%2,%3};"
        : "+f"(c[0]), "+f"(c[1]), "+f"(c[2]), "+f"(c[3])
        : "r"(__float_as_uint(a0)), "r"(__float_as_uint(a1)),
          "r"(__float_as_uint(a2)), "r"(__float_as_uint(a3)),
          "r"(__float_as_uint(b0)), "r"(__float_as_uint(b1)));
}

#define KC 96
#define NCHUNK 8
#define SA_STR 100
#define SB_STR 100
#define SMEM_FLOATS (64 * SA_STR + 32 * SB_STR + 32)   // 9632 = 38.5KB

__global__ void k_reset() {
    if (threadIdx.x < 256) g_flag[threadIdx.x] = 0;
    if (threadIdx.x == 0)  g_aux = 0;
}

// =====================================================================
// Fused kernel. Grid: [0,3nb) proj GEMM tiles | [3nb,3nb+cb) cet GEMM |
// [totJobs, totJobs+MB) mlp blocks (co-resident; wait on tile flags).
// 128 threads everywhere; static smem 38.5KB -> 4 blocks/SM.
// =====================================================================
__global__ void __launch_bounds__(128) k_fused(
    const float* __restrict__ place, const float* __restrict__ other,
    const float* __restrict__ doc,  const float* __restrict__ cemb,
    const float* __restrict__ Wt2c, const float* __restrict__ bt2c,
    const float* __restrict__ Wcode, const float* __restrict__ bcode,
    const float* __restrict__ Wctx, const float* __restrict__ bctx,
    const float* __restrict__ Wcet, const float* __restrict__ bcet,
    const float* __restrict__ codeTab,
    const int* __restrict__ fcodes, const int* __restrict__ ccodes,
    const float* __restrict__ gaz,
    const float* __restrict__ W1, const float* __restrict__ b1,
    const float* __restrict__ W2, const float* __restrict__ b2,
    const float* __restrict__ WL, const float* __restrict__ bL,
    float* __restrict__ out,
    int nb, int cb, int B, int nCtry)
{
    __shared__ __align__(16) float smem[SMEM_FLOATS];
    const int bid = blockIdx.x;
    const int tid = threadIdx.x;
    const int warp = tid >> 5, lane = tid & 31;
    const int totJobs = 3 * nb + cb;

    if (bid < totJobs) {
        // ================= TF32 MMA GEMM job =================
        float* sA = smem;
        float* sB = smem + 64 * SA_STR;
        float* sBias = smem + 64 * SA_STR + 32 * SB_STR;
        const int gid = lane >> 2, tig = lane & 3;

        int job, rb;
        if      (bid <     nb) { job = 0; rb = bid; }
        else if (bid < 2 * nb) { job = 1; rb = bid - nb; }
        else if (bid < 3 * nb) { job = 2; rb = bid - 2 * nb; }
        else                   { job = 3; rb = bid - 3 * nb; }
        const int rowbase = rb * 64;
        const int nRows = (job == 3) ? nCtry : B;
        const float* src = (job == 0) ? place : (job == 1) ? other
                         : (job == 2) ? doc   : cemb;

        if (tid < 32) {
            float bv;
            if      (job == 0) bv = (tid < 24) ? bt2c[tid] : bcode[tid - 24];
            else if (job == 3) bv = (tid < 24) ? bcet[tid] : 0.f;
            else               bv = (tid < 24) ? bctx[tid] : 0.f;
            sBias[tid] = bv;
        }

        float c[4][4];
        #pragma unroll
        for (int i = 0; i < 4; i++)
            #pragma unroll
            for (int j = 0; j < 4; j++) c[i][j] = 0.f;

        #pragma unroll 1
        for (int ch = 0; ch < NCHUNK; ch++) {
            const int k0 = ch * KC;
            __syncthreads();
            #pragma unroll
            for (int i = 0; i < 12; i++) {
                int idx = tid + i * 128;
                int r = idx / 24, c4 = idx - r * 24;
                int gr = min(rowbase + r, nRows - 1);
                float4 v = __ldg((const float4*)(src + (size_t)gr * BERT + k0 + c4 * 4));
                float* d = sA + r * SA_STR + c4 * 4;
                d[0] = to_tf32(v.x); d[1] = to_tf32(v.y);
                d[2] = to_tf32(v.z); d[3] = to_tf32(v.w);
            }
            #pragma unroll
            for (int i = 0; i < 6; i++) {
                int idx = tid + i * 128;
                int n = idx / 24, c4 = idx - n * 24;
                const float* wr;
                if      (job == 0) wr = (n < 24) ? Wt2c + n * BERT
                                                 : Wcode + (n - 24) * BERT;
                else if (job == 3) wr = Wcet + min(n, 23) * BERT;
                else               wr = Wctx + min(n, 23) * BERT;
                float4 v = __ldg((const float4*)(wr + k0 + c4 * 4));
                float* d = sB + n * SB_STR + c4 * 4;
                d[0] = to_tf32(v.x); d[1] = to_tf32(v.y);
                d[2] = to_tf32(v.z); d[3] = to_tf32(v.w);
            }
            __syncthreads();
            const float* pa = sA + (warp * 16 + gid) * SA_STR + tig;
            #pragma unroll
            for (int kk = 0; kk < 12; kk++) {
                int kb = kk * 8;
                float a0 = pa[kb];
                float a1 = pa[8 * SA_STR + kb];
                float a2 = pa[kb + 4];
                float a3 = pa[8 * SA_STR + kb + 4];
                #pragma unroll
                for (int nt = 0; nt < 4; nt++) {
                    const float* pb = sB + (nt * 8 + gid) * SB_STR + kb + tig;
                    mma_tf32(c[nt], a0, a1, a2, a3, pb[0], pb[4]);
                }
            }
        }

        const int r0 = rowbase + warp * 16 + gid;
        const int r1 = r0 + 8;
        if (job < 3) {
            const int colbase = (job == 0) ? 0 : (job == 1) ? 32 : 56;
            const int ntMax = (job == 0) ? 4 : 3;
            #pragma unroll
            for (int nt = 0; nt < 4; nt++) {
                if (nt >= ntMax) break;
                int n0 = nt * 8 + 2 * tig;
                float b0 = sBias[n0], b1 = sBias[n0 + 1];
                if (r0 < B)
                    *(float2*)&g_proj[r0 * 80 + colbase + n0] =
                        make_float2(c[nt][0] + b0, c[nt][1] + b1);
                if (r1 < B)
                    *(float2*)&g_proj[r1 * 80 + colbase + n0] =
                        make_float2(c[nt][2] + b0, c[nt][3] + b1);
            }
        } else {
            float s0 = 0.f, s1 = 0.f;
            #pragma unroll
            for (int nt = 0; nt < 3; nt++) {
                int n0 = nt * 8 + 2 * tig;
                float b0 = sBias[n0], b1 = sBias[n0 + 1];
                float v00 = c[nt][0] + b0, v01 = c[nt][1] + b1;
                float v10 = c[nt][2] + b0, v11 = c[nt][3] + b1;
                if (r0 < nCtry)
                    *(float2*)&g_cet[r0 * CTRY + n0] = make_float2(v00, v01);
                if (r1 < nCtry)
                    *(float2*)&g_cet[r1 * CTRY + n0] = make_float2(v10, v11);
                s0 += v00 * v00 + v01 * v01;
                s1 += v10 * v10 + v11 * v11;
            }
            s0 += __shfl_xor_sync(0xffffffffu, s0, 1);
            s0 += __shfl_xor_sync(0xffffffffu, s0, 2);
            s1 += __shfl_xor_sync(0xffffffffu, s1, 1);
            s1 += __shfl_xor_sync(0xffffffffu, s1, 2);
            if (tig == 0) {
                if (r0 < nCtry) g_cetn[r0] = sqrtf(s0);
                if (r1 < nCtry) g_cetn[r1] = sqrtf(s1);
            }
        }
        // publish
        __threadfence();
        __syncthreads();
        if (tid == 0) {
            if (job < 3) *(volatile int*)&g_flag[bid] = 1;
            else         atomicAdd(&g_aux, 1);
        }
        return;
    }

    // ================= MLP block (4 rows x 32 lanes, 2 cands/thr) =====
    {
        float* sW1T = smem;              // 320
        float* sW2  = smem + 320;        // 576
        float* sB1  = smem + 896;        // 24
        float* sB2  = smem + 920;
        float* sWL  = smem + 944;
        float* sbLp = smem + 968;
        float* sN   = smem + 976;        // 16
        float* sX   = smem + 1024;       // 320
        float* sGaz = smem + 1344;       // 2304

        const int mb = bid - totJobs;
        const int b0 = mb * 4;

        // ---- stage everything that does NOT depend on proj ----
        for (int i = tid; i < NFEAT * MIX; i += 128) {
            int q = i / MIX, j = i - q * MIX;
            sW1T[i] = W1[j * NFEAT + q];
        }
        for (int i = tid; i < MIX * MIX; i += 128) sW2[i] = W2[i];
        if (tid < MIX) { sB1[tid] = b1[tid]; sB2[tid] = b2[tid]; sWL[tid] = WL[tid]; }
        if (tid == 0) sbLp[0] = bL[0];
        {
            int cnt = min(576, (B - b0) * 144);
            const float4* gp = (const float4*)gaz + (size_t)b0 * 144;
            float4* sp = (float4*)sGaz;
            for (int i = tid; i < cnt; i += 128) sp[i] = __ldg(gp + i);
        }

        // ---- wait for the 3 proj tiles covering rows b0..b0+3, + cet ----
        if (tid == 0) {
            int rb = b0 >> 6;
            while (!(*(volatile int*)&g_flag[rb] &&
                     *(volatile int*)&g_flag[nb + rb] &&
                     *(volatile int*)&g_flag[2 * nb + rb]))
                __nanosleep(64);
            while (*(volatile int*)&g_aux < cb) __nanosleep(64);
        }
        __syncthreads();
        __threadfence();

        for (int i = tid; i < 4 * 80; i += 128) {
            int bb = min(b0 + i / 80, B - 1);
            sX[i] = g_proj[bb * 80 + (i % 80)];
        }
        __syncthreads();

        if (tid < 16) {
            int gg = tid >> 2, which = tid & 3;
            int off = (which == 0) ? 0 : (which == 1) ? 24 : (which == 2) ? 32 : 56;
            int cnt = (which == 1) ? CODE : CTRY;
            float ss = 0.f;
            for (int j = 0; j < cnt; j++) { float v = sX[gg * 80 + off + j]; ss += v * v; }
            sN[gg * 4 + which] = fmaxf(sqrtf(ss), 1e-8f);
        }
        __syncthreads();

        const int g = tid >> 5;
        const int b = min(b0 + g, B - 1);
        const int idx0 = b * CMAX + lane;
        const int idx1 = idx0 + 32;
        const int fc0 = fcodes[idx0], cc0 = ccodes[idx0];
        const int fc1 = fcodes[idx1], cc1 = ccodes[idx1];
        const float* sx = sX + g * 80;

        const ulonglong2* cet0 = (const ulonglong2*)(g_cet + cc0 * CTRY);
        const ulonglong2* cet1 = (const ulonglong2*)(g_cet + cc1 * CTRY);
        const u64* x1 = (const u64*)(sx);
        const u64* x3 = (const u64*)(sx + 32);
        const u64* x4 = (const u64*)(sx + 56);
        u64 p10=0, p30=0, p40=0, p11=0, p31=0, p41=0;
        #pragma unroll
        for (int j = 0; j < 6; j++) {
            ulonglong2 c0 = __ldg(cet0 + j);
            ulonglong2 c1 = __ldg(cet1 + j);
            u64 xa = x1[2*j], xb = x1[2*j+1];
            ffma2(p10, xa, c0.x); ffma2(p10, xb, c0.y);
            ffma2(p11, xa, c1.x); ffma2(p11, xb, c1.y);
            xa = x3[2*j]; xb = x3[2*j+1];
            ffma2(p30, xa, c0.x); ffma2(p30, xb, c0.y);
            ffma2(p31, xa, c1.x); ffma2(p31, xb, c1.y);
            xa = x4[2*j]; xb = x4[2*j+1];
            ffma2(p40, xa, c0.x); ffma2(p40, xb, c0.y);
            ffma2(p41, xa, c1.x); ffma2(p41, xb, c1.y);
        }
        const ulonglong2* fe0 = (const ulonglong2*)(codeTab + fc0 * CODE);
        const ulonglong2* fe1 = (const ulonglong2*)(codeTab + fc1 * CODE);
        const u64* x2p = (const u64*)(sx + 24);
        u64 p20 = 0, p21 = 0;
        float n20 = 0.f, n21 = 0.f;      // inline code-embedding norms
        #pragma unroll
        for (int j = 0; j < 2; j++) {
            ulonglong2 c0 = __ldg(fe0 + j);
            ulonglong2 c1 = __ldg(fe1 + j);
            u64 xa = x2p[2*j], xb = x2p[2*j+1];
            ffma2(p20, xa, c0.x); ffma2(p20, xb, c0.y);
            ffma2(p21, xa, c1.x); ffma2(p21, xb, c1.y);
            n20 += sumsq2(c0.x) + sumsq2(c0.y);
            n21 += sumsq2(c1.x) + sumsq2(c1.y);
        }
        float nb0 = fmaxf(g_cetn[cc0], 1e-8f);
        float nb1 = fmaxf(g_cetn[cc1], 1e-8f);
        float feat0[4], feat1[4];
        feat0[0] = __fdividef(hsum2(p10), sN[g*4+0] * nb0);
        feat0[1] = __fdividef(hsum2(p20), sN[g*4+1] * fmaxf(sqrtf(n20), 1e-8f));
        feat0[2] = __fdividef(hsum2(p30), sN[g*4+2] * nb0);
        feat0[3] = __fdividef(hsum2(p40), sN[g*4+3] * nb0);
        feat1[0] = __fdividef(hsum2(p11), sN[g*4+0] * nb1);
        feat1[1] = __fdividef(hsum2(p21), sN[g*4+1] * fmaxf(sqrtf(n21), 1e-8f));
        feat1[2] = __fdividef(hsum2(p31), sN[g*4+2] * nb1);
        feat1[3] = __fdividef(hsum2(p41), sN[g*4+3] * nb1);

        u64 a0[12], a1[12];
        const u64* b1p = (const u64*)sB1;
        #pragma unroll
        for (int j = 0; j < 12; j++) { a0[j] = b1p[j]; a1[j] = b1p[j]; }

        const float* gz0 = sGaz + ((g * CMAX) + lane) * GAZ;
        const float* gz1 = gz0 + 32 * GAZ;
        #pragma unroll
        for (int q = 0; q < NFEAT; q++) {
            float f0 = (q < 4) ? feat0[q] : gz0[q - 4];
            float f1 = (q < 4) ? feat1[q] : gz1[q - 4];
            u64 ff0 = pack2(f0, f0), ff1 = pack2(f1, f1);
            const ulonglong2* wc = (const ulonglong2*)(sW1T + q * MIX);
            #pragma unroll
            for (int j2 = 0; j2 < 6; j2++) {
                ulonglong2 wv = wc[j2];
                ffma2(a0[2*j2],   ff0, wv.x); ffma2(a0[2*j2+1], ff0, wv.y);
                ffma2(a1[2*j2],   ff1, wv.x); ffma2(a1[2*j2+1], ff1, wv.y);
            }
        }
        #pragma unroll
        for (int j = 0; j < 12; j++) {
            float lo, hi;
            unpack2(a0[j], lo, hi); a0[j] = pack2(sigf(lo), sigf(hi));
            unpack2(a1[j], lo, hi); a1[j] = pack2(sigf(lo), sigf(hi));
        }

        float last0 = sbLp[0], last1 = sbLp[0];
        #pragma unroll
        for (int j = 0; j < MIX; j++) {
            const ulonglong2* wr = (const ulonglong2*)(sW2 + j * MIX);
            u64 s0 = 0ull, s1 = 0ull;
            #pragma unroll
            for (int q2 = 0; q2 < 6; q2++) {
                ulonglong2 wv = wr[q2];
                ffma2(s0, a0[2*q2],   wv.x); ffma2(s0, a0[2*q2+1], wv.y);
                ffma2(s1, a1[2*q2],   wv.x); ffma2(s1, a1[2*q2+1], wv.y);
            }
            float v0 = sB2[j] + hsum2(s0);
            float v1 = sB2[j] + hsum2(s1);
            last0 = fmaf(sWL[j], sigf(v0), last0);
            last1 = fmaf(sWL[j], sigf(v1), last1);
        }

        float m = fmaxf(last0, last1);
        #pragma unroll
        for (int o = 16; o; o >>= 1) m = fmaxf(m, __shfl_xor_sync(0xffffffffu, m, o));
        float e0 = __expf(last0 - m);
        float e1 = __expf(last1 - m);
        float ss = e0 + e1;
        #pragma unroll
        for (int o = 16; o; o >>= 1) ss += __shfl_xor_sync(0xffffffffu, ss, o);
        float inv = __fdividef(1.f, ss);
        if (b0 + g < B) {
            out[idx0] = e0 * inv;
            out[idx1] = e1 * inv;
        }
    }
}

// =====================================================================
extern "C" void kernel_launch(void* const* d_in, const int* in_sizes, int n_in,
                              void* d_out, int out_size)
{
    const float* place  = (const float*)d_in[0];
    const float* other  = (const float*)d_in[1];
    const float* doc    = (const float*)d_in[2];
    const int*   fcodes = (const int*)  d_in[3];
    const int*   ccodes = (const int*)  d_in[4];
    const float* gaz    = (const float*)d_in[5];
    const float* codeTab= (const float*)d_in[6];
    const float* ctryTab= (const float*)d_in[7];
    const float* Wcet   = (const float*)d_in[8];
    const float* bcet   = (const float*)d_in[9];
    const float* Wt2c   = (const float*)d_in[10];
    const float* bt2c   = (const float*)d_in[11];
    const float* Wctx   = (const float*)d_in[12];
    const float* bctx   = (const float*)d_in[13];
    const float* Wcode  = (const float*)d_in[14];
    const float* bcode  = (const float*)d_in[15];
    const float* W1     = (const float*)d_in[16];
    const float* b1     = (const float*)d_in[17];
    const float* W2     = (const float*)d_in[18];
    const float* b2     = (const float*)d_in[19];
    const float* WL     = (const float*)d_in[20];
    const float* bL     = (const float*)d_in[21];
    float* out = (float*)d_out;

    int B      = in_sizes[0] / BERT;
    int nCtry  = in_sizes[7] / BERT;

    int nb = (B + 63) / 64;           // proj tiles per job
    int cb = (nCtry + 63) / 64;       // cet tiles
    int MB = (B + 3) / 4;             // mlp blocks
    int grid = 3 * nb + cb + MB;

    k_reset<<<1, 256>>>();
    k_fused<<<grid, 128>>>(place, other, doc, ctryTab,
                           Wt2c, bt2c, Wcode, bcode, Wctx, bctx,
                           Wcet, bcet, codeTab, fcodes, ccodes, gaz,
                           W1, b1, W2, b2, WL, bL, out,
                           nb, cb, B, nCtry);
}